// round 14
// baseline (speedup 1.0000x reference)
#include <cuda_runtime.h>
#include <cuda_bf16.h>
#include <cuda_fp16.h>
#include <math.h>
#include <stdint.h>

#define NATOMS 50000
#define NEDGES 800000
#define ELEM   64
#define DOUT   128
#define BN_EPS 1e-5f
#define NTILES (NEDGES / 128)     // 6250
#define GRID_Y 296                // persistent, 2 CTAs/SM

// ---------------- scratch (device globals; no allocation allowed) ----------------
__device__ __half g_P1h[(size_t)NATOMS * DOUT];  // atom @ W1 + b (fp16)
__device__ __half g_P2h[(size_t)NATOMS * DOUT];  // atom @ W2     (fp16)
__device__ __half g_Yh[(size_t)NEDGES * DOUT];   // pre-BN edge features, fp16
__device__ int    g_rowptr[NATOMS + 1];
__device__ float  g_colsum[DOUT];
__device__ float  g_colsq [DOUT];
__device__ float  g_a1[DOUT], g_c1[DOUT];
__device__ float  g_sumed[(size_t)NATOMS * ELEM];
__device__ float  g_s2[ELEM], g_q2[ELEM];
__device__ float  g_a2[ELEM], g_c2[ELEM];

// ---------------- helpers ----------------
__device__ __forceinline__ float softplusf(float x) {
    return log1pf(expf(-fabsf(x))) + fmaxf(x, 0.0f);
}
// round-11 gate (fast-math, short chain)
__device__ __forceinline__ float msg_gate(float yf, float yc) {
    float ef  = __expf(-yf);
    float sig = __fdividef(1.0f, 1.0f + ef);
    float ec  = __expf(-fabsf(yc));
    float sp  = __logf(1.0f + ec) + fmaxf(yc, 0.0f);
    return sig * sp;
}
__device__ __forceinline__ void mma_bf16(float4& d, uint32_t a0, uint32_t a1,
                                         uint32_t a2, uint32_t a3,
                                         uint32_t b0, uint32_t b1) {
    asm volatile(
        "mma.sync.aligned.m16n8k16.row.col.f32.bf16.bf16.f32 "
        "{%0,%1,%2,%3}, {%4,%5,%6,%7}, {%8,%9}, {%0,%1,%2,%3};"
        : "+f"(d.x), "+f"(d.y), "+f"(d.z), "+f"(d.w)
        : "r"(a0), "r"(a1), "r"(a2), "r"(a3), "r"(b0), "r"(b1));
}
__device__ __forceinline__ uint32_t bf2_bits(__nv_bfloat162 h) {
    return *reinterpret_cast<uint32_t*>(&h);
}
__device__ __forceinline__ uint32_t h2_bits(__half2 h) {
    return *reinterpret_cast<uint32_t*>(&h);
}

// ---------------- SMEM layout (bytes), shared by k_y_mma and k_pre_mma ----------------
#define LDAB 72           // bf16 A leading dim (144B rows -> conflict-free lds.32)
#define NPAD 20           // B packed: uint4 slots per n (320B stride)
#define SM_SIDX 0         // 128 ints
#define SM_NIDX 512
#define SM_AH   1024      // 128 x LDAB bf16 = 18432
#define SM_AL   19456     // 128 x LDAB bf16 = 18432
#define SM_BP   37888     // packed B: 128 x NPAD x 16B = 40960
#define SM_TOTAL 78848    // 77 KB -> 2 CTAs/SM

// ---------------- kernels ----------------
__global__ void k_init() {
    int t = threadIdx.x;
    if (t < DOUT) { g_colsum[t] = 0.f; g_colsq[t] = 0.f; }
    if (t < ELEM) { g_s2[t] = 0.f; g_q2[t] = 0.f; }
}

__global__ void k_rowptr(const int* __restrict__ sidx) {
    int a = blockIdx.x * blockDim.x + threadIdx.x;
    if (a > NATOMS) return;
    int lo = 0, hi = NEDGES;
    while (lo < hi) {
        int mid = (lo + hi) >> 1;
        if (sidx[mid] < a) lo = mid + 1; else hi = mid;
    }
    g_rowptr[a] = lo;
}

// Precompute via HMMA: P1 = atom @ W[0:64] + b (phase 0), P2 = atom @ W[64:128].
__global__ void __launch_bounds__(256, 2) k_pre_mma(const float* __restrict__ atom,
                                                    const float* __restrict__ W,
                                                    const float* __restrict__ bias) {
    extern __shared__ char sm[];
    __nv_bfloat16* sAh = (__nv_bfloat16*)(sm + SM_AH);
    __nv_bfloat16* sAl = (__nv_bfloat16*)(sm + SM_AL);
    uint4* sBp = (uint4*)(sm + SM_BP);

    const int tid  = threadIdx.x;
    const int wid  = tid >> 5;
    const int lane = tid & 31;
    const int wm   = wid >> 1;
    const int wn   = wid & 1;
    const int g    = lane >> 2;
    const int tg   = lane & 3;
    const int colbase = wn * 64 + tg * 16;

    const int ab = blockIdx.x * 128;
    const int nvalid = min(128, NATOMS - ab);

    #pragma unroll
    for (int p = 0; p < 8; p++) {
        int i4 = tid + p * 256;
        int row = i4 >> 4, kv = i4 & 15;
        float4 v = make_float4(0.f, 0.f, 0.f, 0.f);
        if (row < nvalid)
            v = __ldg((const float4*)(atom + (size_t)(ab + row) * ELEM + kv * 4));
        __nv_bfloat162 h0 = __float22bfloat162_rn(make_float2(v.x, v.y));
        __nv_bfloat162 h1 = __float22bfloat162_rn(make_float2(v.z, v.w));
        __nv_bfloat162 l0 = __float22bfloat162_rn(make_float2(
            v.x - __bfloat162float(__low2bfloat16(h0)),
            v.y - __bfloat162float(__high2bfloat16(h0))));
        __nv_bfloat162 l1 = __float22bfloat162_rn(make_float2(
            v.z - __bfloat162float(__low2bfloat16(h1)),
            v.w - __bfloat162float(__high2bfloat16(h1))));
        int o = row * LDAB + kv * 4;
        uint2 oh; oh.x = bf2_bits(h0); oh.y = bf2_bits(h1);
        uint2 ol; ol.x = bf2_bits(l0); ol.y = bf2_bits(l1);
        *(uint2*)(sAh + o) = oh;
        *(uint2*)(sAl + o) = ol;
    }

    float4 bj[4];
    #pragma unroll
    for (int q = 0; q < 4; q++)
        bj[q] = __ldg((const float4*)(bias + colbase + q * 4));

    for (int phase = 0; phase < 2; phase++) {
        #pragma unroll
        for (int it = 0; it < 8; it++) {
            int idx = it * 256 + tid;
            int n   = idx >> 4;
            int ks  = (idx >> 2) & 3;
            int tgq = idx & 3;
            int h = n >> 6, pp = n & 63;
            int l = ((pp >> 1) & 3) * 16 + (pp >> 3) * 2 + (pp & 1);
            int col = h * 64 + l;
            int k0 = ks * 16 + tgq * 2;
            float v0 = W[(size_t)(phase * 64 + k0)     * DOUT + col];
            float v1 = W[(size_t)(phase * 64 + k0 + 1) * DOUT + col];
            float v2 = W[(size_t)(phase * 64 + k0 + 8) * DOUT + col];
            float v3 = W[(size_t)(phase * 64 + k0 + 9) * DOUT + col];
            __nv_bfloat162 h01 = __float22bfloat162_rn(make_float2(v0, v1));
            __nv_bfloat162 h23 = __float22bfloat162_rn(make_float2(v2, v3));
            __nv_bfloat162 l01 = __float22bfloat162_rn(make_float2(
                v0 - __bfloat162float(__low2bfloat16(h01)), v1 - __bfloat162float(__high2bfloat16(h01))));
            __nv_bfloat162 l23 = __float22bfloat162_rn(make_float2(
                v2 - __bfloat162float(__low2bfloat16(h23)), v3 - __bfloat162float(__high2bfloat16(h23))));
            uint4 o;
            o.x = bf2_bits(h01); o.y = bf2_bits(h23);
            o.z = bf2_bits(l01); o.w = bf2_bits(l23);
            sBp[(size_t)n * NPAD + ks * 4 + tgq] = o;
        }
        __syncthreads();

        float4 acc[2][8];
        #pragma unroll
        for (int i = 0; i < 2; i++)
            #pragma unroll
            for (int j = 0; j < 8; j++)
                acc[i][j] = make_float4(0.f, 0.f, 0.f, 0.f);

        #pragma unroll
        for (int ks = 0; ks < 4; ks++) {
            const int c0 = ks * 16 + tg * 2;
            uint32_t ah[2][4], al[2][4];
            #pragma unroll
            for (int i = 0; i < 2; i++) {
                const __nv_bfloat16* rh = sAh + (wm * 32 + i * 16 + g) * LDAB;
                const __nv_bfloat16* rl = sAl + (wm * 32 + i * 16 + g) * LDAB;
                ah[i][0] = *(const uint32_t*)(rh + c0);
                ah[i][1] = *(const uint32_t*)(rh + 8 * LDAB + c0);
                ah[i][2] = *(const uint32_t*)(rh + c0 + 8);
                ah[i][3] = *(const uint32_t*)(rh + 8 * LDAB + c0 + 8);
                al[i][0] = *(const uint32_t*)(rl + c0);
                al[i][1] = *(const uint32_t*)(rl + 8 * LDAB + c0);
                al[i][2] = *(const uint32_t*)(rl + c0 + 8);
                al[i][3] = *(const uint32_t*)(rl + 8 * LDAB + c0 + 8);
            }
            #pragma unroll
            for (int j = 0; j < 8; j++) {
                const int n = wn * 64 + j * 8 + g;
                uint4 bb = sBp[(size_t)n * NPAD + ks * 4 + tg];
                #pragma unroll
                for (int i = 0; i < 2; i++) {
                    mma_bf16(acc[i][j], ah[i][0], ah[i][1], ah[i][2], ah[i][3], bb.x, bb.y);
                    mma_bf16(acc[i][j], ah[i][0], ah[i][1], ah[i][2], ah[i][3], bb.z, bb.w);
                    mma_bf16(acc[i][j], al[i][0], al[i][1], al[i][2], al[i][3], bb.x, bb.y);
                }
            }
        }

        __half* Pdst = (phase == 0) ? g_P1h : g_P2h;
        #pragma unroll
        for (int i = 0; i < 2; i++) {
            #pragma unroll
            for (int rr = 0; rr < 2; rr++) {
                const int row = wm * 32 + i * 16 + rr * 8 + g;
                if (row < nvalid) {
                    uint32_t hb[8];
                    #pragma unroll
                    for (int j = 0; j < 8; j++) {
                        float y0 = (rr ? acc[i][j].z : acc[i][j].x);
                        float y1 = (rr ? acc[i][j].w : acc[i][j].y);
                        if (phase == 0) {
                            float bx = (j & 1) ? bj[j >> 1].z : bj[j >> 1].x;
                            float by = (j & 1) ? bj[j >> 1].w : bj[j >> 1].y;
                            y0 += bx; y1 += by;
                        }
                        hb[j] = h2_bits(__floats2half2_rn(y0, y1));
                    }
                    uint4 o0 = make_uint4(hb[0], hb[1], hb[2], hb[3]);
                    uint4 o1 = make_uint4(hb[4], hb[5], hb[6], hb[7]);
                    __half* dst = Pdst + (size_t)(ab + row) * DOUT + colbase;
                    *(uint4*)dst       = o0;
                    *(uint4*)(dst + 8) = o1;
                }
            }
        }
        __syncthreads();
    }
}

// Pass 1 (raw HMMA): unchanged from round 13.
__global__ void __launch_bounds__(256, 2) k_y_mma(const float* __restrict__ nbr,
                                                  const int* __restrict__ sidx,
                                                  const int* __restrict__ nidx,
                                                  const float* __restrict__ W) {
    extern __shared__ char sm[];
    int*   s_sidx = (int*)(sm + SM_SIDX);
    int*   s_nidx = (int*)(sm + SM_NIDX);
    __nv_bfloat16* sAh = (__nv_bfloat16*)(sm + SM_AH);
    __nv_bfloat16* sAl = (__nv_bfloat16*)(sm + SM_AL);
    uint4* sBp = (uint4*)(sm + SM_BP);

    const int tid  = threadIdx.x;
    const int wid  = tid >> 5;
    const int lane = tid & 31;
    const int wm   = wid >> 1;
    const int wn   = wid & 1;
    const int g    = lane >> 2;
    const int tg   = lane & 3;

    #pragma unroll
    for (int it = 0; it < 8; it++) {
        int idx = it * 256 + tid;
        int n   = idx >> 4;
        int ks  = (idx >> 2) & 3;
        int tgq = idx & 3;
        int h = n >> 6, pp = n & 63;
        int l = ((pp >> 1) & 3) * 16 + (pp >> 3) * 2 + (pp & 1);
        int col = h * 64 + l;
        int k0 = ks * 16 + tgq * 2;
        float v0 = W[(size_t)(128 + k0)     * DOUT + col];
        float v1 = W[(size_t)(128 + k0 + 1) * DOUT + col];
        float v2 = W[(size_t)(128 + k0 + 8) * DOUT + col];
        float v3 = W[(size_t)(128 + k0 + 9) * DOUT + col];
        __nv_bfloat162 h01 = __float22bfloat162_rn(make_float2(v0, v1));
        __nv_bfloat162 h23 = __float22bfloat162_rn(make_float2(v2, v3));
        __nv_bfloat162 l01 = __float22bfloat162_rn(make_float2(
            v0 - __bfloat162float(__low2bfloat16(h01)), v1 - __bfloat162float(__high2bfloat16(h01))));
        __nv_bfloat162 l23 = __float22bfloat162_rn(make_float2(
            v2 - __bfloat162float(__low2bfloat16(h23)), v3 - __bfloat162float(__high2bfloat16(h23))));
        uint4 o;
        o.x = bf2_bits(h01); o.y = bf2_bits(h23);
        o.z = bf2_bits(l01); o.w = bf2_bits(l23);
        sBp[(size_t)n * NPAD + ks * 4 + tgq] = o;
    }
    __syncthreads();

    float cs[16], cq[16];
    #pragma unroll
    for (int q = 0; q < 16; q++) { cs[q] = 0.f; cq[q] = 0.f; }
    const int colbase = wn * 64 + tg * 16;

    for (int t = blockIdx.x; t < NTILES; t += GRID_Y) {
        const int eb = t * 128;

        float4 v[8];
        #pragma unroll
        for (int p = 0; p < 8; p++)
            v[p] = __ldcs((const float4*)(nbr + (size_t)eb * ELEM) + tid + p * 256);
        if (tid < 128) {
            s_sidx[tid] = __ldg(sidx + eb + tid);
            s_nidx[tid] = __ldg(nidx + eb + tid);
        }
        #pragma unroll
        for (int p = 0; p < 8; p++) {
            int i4 = tid + p * 256;
            int row = i4 >> 4, kv = i4 & 15;
            __nv_bfloat162 h0 = __float22bfloat162_rn(make_float2(v[p].x, v[p].y));
            __nv_bfloat162 h1 = __float22bfloat162_rn(make_float2(v[p].z, v[p].w));
            __nv_bfloat162 l0 = __float22bfloat162_rn(make_float2(
                v[p].x - __bfloat162float(__low2bfloat16(h0)),
                v[p].y - __bfloat162float(__high2bfloat16(h0))));
            __nv_bfloat162 l1 = __float22bfloat162_rn(make_float2(
                v[p].z - __bfloat162float(__low2bfloat16(h1)),
                v[p].w - __bfloat162float(__high2bfloat16(h1))));
            int o = row * LDAB + kv * 4;
            uint2 oh; oh.x = bf2_bits(h0); oh.y = bf2_bits(h1);
            uint2 ol; ol.x = bf2_bits(l0); ol.y = bf2_bits(l1);
            *(uint2*)(sAh + o) = oh;
            *(uint2*)(sAl + o) = ol;
        }
        __syncthreads();

        float4 acc[2][8];
        #pragma unroll
        for (int i = 0; i < 2; i++)
            #pragma unroll
            for (int j = 0; j < 8; j++)
                acc[i][j] = make_float4(0.f, 0.f, 0.f, 0.f);

        #pragma unroll
        for (int ks = 0; ks < 4; ks++) {
            const int c0 = ks * 16 + tg * 2;
            uint32_t ah[2][4], al[2][4];
            #pragma unroll
            for (int i = 0; i < 2; i++) {
                const __nv_bfloat16* rh = sAh + (wm * 32 + i * 16 + g) * LDAB;
                const __nv_bfloat16* rl = sAl + (wm * 32 + i * 16 + g) * LDAB;
                ah[i][0] = *(const uint32_t*)(rh + c0);
                ah[i][1] = *(const uint32_t*)(rh + 8 * LDAB + c0);
                ah[i][2] = *(const uint32_t*)(rh + c0 + 8);
                ah[i][3] = *(const uint32_t*)(rh + 8 * LDAB + c0 + 8);
                al[i][0] = *(const uint32_t*)(rl + c0);
                al[i][1] = *(const uint32_t*)(rl + 8 * LDAB + c0);
                al[i][2] = *(const uint32_t*)(rl + c0 + 8);
                al[i][3] = *(const uint32_t*)(rl + 8 * LDAB + c0 + 8);
            }
            #pragma unroll
            for (int j = 0; j < 8; j++) {
                const int n = wn * 64 + j * 8 + g;
                uint4 bb = sBp[(size_t)n * NPAD + ks * 4 + tg];
                #pragma unroll
                for (int i = 0; i < 2; i++) {
                    mma_bf16(acc[i][j], ah[i][0], ah[i][1], ah[i][2], ah[i][3], bb.x, bb.y);
                    mma_bf16(acc[i][j], ah[i][0], ah[i][1], ah[i][2], ah[i][3], bb.z, bb.w);
                    mma_bf16(acc[i][j], al[i][0], al[i][1], al[i][2], al[i][3], bb.x, bb.y);
                }
            }
        }

        #pragma unroll
        for (int i = 0; i < 2; i++) {
            #pragma unroll
            for (int rr = 0; rr < 2; rr++) {
                const int row = wm * 32 + i * 16 + rr * 8 + g;
                const int s = s_sidx[row], n = s_nidx[row];
                uint4 p1u[2], p2u[2];
                p1u[0] = __ldg((const uint4*)(g_P1h + (size_t)s * DOUT + colbase));
                p1u[1] = __ldg((const uint4*)(g_P1h + (size_t)s * DOUT + colbase + 8));
                p2u[0] = __ldg((const uint4*)(g_P2h + (size_t)n * DOUT + colbase));
                p2u[1] = __ldg((const uint4*)(g_P2h + (size_t)n * DOUT + colbase + 8));
                const __half2* ph1 = (const __half2*)p1u;
                const __half2* ph2 = (const __half2*)p2u;
                uint32_t hb[8];
                #pragma unroll
                for (int j = 0; j < 8; j++) {
                    float2 p1 = __half22float2(ph1[j]);
                    float2 p2 = __half22float2(ph2[j]);
                    float y0 = (rr ? acc[i][j].z : acc[i][j].x) + p1.x + p2.x;
                    float y1 = (rr ? acc[i][j].w : acc[i][j].y) + p1.y + p2.y;
                    cs[2 * j]     += y0; cq[2 * j]     += y0 * y0;
                    cs[2 * j + 1] += y1; cq[2 * j + 1] += y1 * y1;
                    hb[j] = h2_bits(__floats2half2_rn(y0, y1));
                }
                float4 o0 = make_float4(__uint_as_float(hb[0]), __uint_as_float(hb[1]),
                                        __uint_as_float(hb[2]), __uint_as_float(hb[3]));
                float4 o1 = make_float4(__uint_as_float(hb[4]), __uint_as_float(hb[5]),
                                        __uint_as_float(hb[6]), __uint_as_float(hb[7]));
                __half* yr = g_Yh + (size_t)(eb + row) * DOUT + colbase;
                __stcs((float4*)yr, o0);
                __stcs((float4*)(yr + 8), o1);
            }
        }
        __syncthreads();
    }

    #pragma unroll
    for (int q = 0; q < 16; q++) {
        cs[q] += __shfl_xor_sync(0xffffffff, cs[q], 4);
        cs[q] += __shfl_xor_sync(0xffffffff, cs[q], 8);
        cs[q] += __shfl_xor_sync(0xffffffff, cs[q], 16);
        cq[q] += __shfl_xor_sync(0xffffffff, cq[q], 4);
        cq[q] += __shfl_xor_sync(0xffffffff, cq[q], 8);
        cq[q] += __shfl_xor_sync(0xffffffff, cq[q], 16);
    }
    if (g == 0) {
        #pragma unroll
        for (int q = 0; q < 16; q++) {
            atomicAdd(&g_colsum[colbase + q], cs[q]);
            atomicAdd(&g_colsq[colbase + q],  cq[q]);
        }
    }
}

__global__ void k_bn1fin(const float* __restrict__ gamma, const float* __restrict__ beta) {
    int j = threadIdx.x;
    float mean = g_colsum[j] * (1.0f / NEDGES);
    float var  = g_colsq[j] * (1.0f / NEDGES) - mean * mean;
    float aa = gamma[j] * rsqrtf(var + BN_EPS);
    g_a1[j] = aa;
    g_c1[j] = beta[j] - mean * aa;
}

// Pass 2: BN1 + gate + CSR segment sum + fused BN2 stats.
// TWO warps per atom (warp-half h takes edges e0+h*4+quarter, stride 8);
// partial sums combined in a 4x64 smem accumulator; coalesced write-out.
__global__ void __launch_bounds__(256) k_msg() {
    __shared__ float sAcc[4][ELEM];
    __shared__ float sS[ELEM], sQ[ELEM];
    const int tid  = threadIdx.x;
    const int lane = tid & 31;
    const int wid  = tid >> 5;
    const int aw   = wid >> 1;     // atom slot 0..3
    const int half = wid & 1;      // which warp of the pair
    const int a = blockIdx.x * 4 + aw;   // grid*4 == NATOMS exactly

    if (tid < ELEM) { sS[tid] = 0.f; sQ[tid] = 0.f; }
    sAcc[tid >> 6][tid & 63] = 0.f;
    __syncthreads();

    const int quarter = lane >> 3;
    const int j8 = lane & 7;

    float a1f[8], c1f[8], a1c[8], c1c[8];
    #pragma unroll
    for (int q = 0; q < 8; q++) {
        int j = 8 * j8 + q;
        a1f[q] = g_a1[j];      c1f[q] = g_c1[j];
        a1c[q] = g_a1[64 + j]; c1c[q] = g_c1[64 + j];
    }

    const int e0 = g_rowptr[a], e1 = g_rowptr[a + 1];
    float s[8];
    #pragma unroll
    for (int q = 0; q < 8; q++) s[q] = 0.f;
    const char* Yb = (const char*)g_Yh;

    int e = e0 + half * 4 + quarter;
    float4 fv, cv;
    if (e < e1) {
        fv = __ldcs((const float4*)(Yb + (size_t)e * 256 + j8 * 16));
        cv = __ldcs((const float4*)(Yb + (size_t)e * 256 + 128 + j8 * 16));
    }
    while (e < e1) {
        const int en = e + 8;
        float4 fvn, cvn;
        if (en < e1) {   // prefetch before the transcendental block
            fvn = __ldcs((const float4*)(Yb + (size_t)en * 256 + j8 * 16));
            cvn = __ldcs((const float4*)(Yb + (size_t)en * 256 + 128 + j8 * 16));
        }
        const __half2* f2 = (const __half2*)&fv;
        const __half2* c2 = (const __half2*)&cv;
        #pragma unroll
        for (int p = 0; p < 4; p++) {
            float yf0 = __low2float(f2[p])  * a1f[2*p]   + c1f[2*p];
            float yc0 = __low2float(c2[p])  * a1c[2*p]   + c1c[2*p];
            s[2*p]   += msg_gate(yf0, yc0);
            float yf1 = __high2float(f2[p]) * a1f[2*p+1] + c1f[2*p+1];
            float yc1 = __high2float(c2[p]) * a1c[2*p+1] + c1c[2*p+1];
            s[2*p+1] += msg_gate(yf1, yc1);
        }
        fv = fvn; cv = cvn; e = en;
    }
    #pragma unroll
    for (int q = 0; q < 8; q++) {
        s[q] += __shfl_xor_sync(0xffffffff, s[q], 8);
        s[q] += __shfl_xor_sync(0xffffffff, s[q], 16);
    }
    if (quarter == 0) {
        #pragma unroll
        for (int q = 0; q < 8; q++)
            atomicAdd(&sAcc[aw][8 * j8 + q], s[q]);   // 2-way collision (half pair)
    }
    __syncthreads();

    // coalesced write-out + BN2 stats: thread (aa, jj) owns one value
    const int aa = tid >> 6, jj = tid & 63;
    float vsum = sAcc[aa][jj];
    g_sumed[(size_t)(blockIdx.x * 4 + aa) * ELEM + jj] = vsum;
    atomicAdd(&sS[jj], vsum);
    atomicAdd(&sQ[jj], vsum * vsum);
    __syncthreads();
    if (tid < ELEM) {
        atomicAdd(&g_s2[tid], sS[tid]);
        atomicAdd(&g_q2[tid], sQ[tid]);
    }
}

__global__ void k_bn2fin(const float* __restrict__ gamma, const float* __restrict__ beta) {
    int j = threadIdx.x;
    float mean = g_s2[j] * (1.0f / NATOMS);
    float var  = g_q2[j] * (1.0f / NATOMS) - mean * mean;
    float aa = gamma[j] * rsqrtf(var + BN_EPS);
    g_a2[j] = aa;
    g_c2[j] = beta[j] - mean * aa;
}

__global__ void k_final(const float* __restrict__ atom, float* __restrict__ out) {
    int i4 = blockIdx.x * blockDim.x + threadIdx.x;
    if (i4 >= NATOMS * ELEM / 4) return;
    int base = i4 * 4;
    int j = base & 63;
    float4 av = *(const float4*)(atom + base);
    float4 sv = *(const float4*)(g_sumed + base);
    float4 o;
    o.x = softplusf(av.x + sv.x * g_a2[j]     + g_c2[j]);
    o.y = softplusf(av.y + sv.y * g_a2[j + 1] + g_c2[j + 1]);
    o.z = softplusf(av.z + sv.z * g_a2[j + 2] + g_c2[j + 2]);
    o.w = softplusf(av.w + sv.w * g_a2[j + 3] + g_c2[j + 3]);
    *(float4*)(out + base) = o;
}

// ---------------- launch ----------------
extern "C" void kernel_launch(void* const* d_in, const int* in_sizes, int n_in,
                              void* d_out, int out_size) {
    const float* atom = (const float*)d_in[0];
    const float* nbr  = (const float*)d_in[1];
    const int*   sidx = (const int*)d_in[2];
    const int*   nidx = (const int*)d_in[3];
    const float* W    = (const float*)d_in[4];
    const float* bias = (const float*)d_in[5];
    const float* g1   = (const float*)d_in[6];
    const float* be1  = (const float*)d_in[7];
    const float* g2   = (const float*)d_in[8];
    const float* be2  = (const float*)d_in[9];
    float* out = (float*)d_out;

    cudaFuncSetAttribute(k_y_mma, cudaFuncAttributeMaxDynamicSharedMemorySize, SM_TOTAL);
    cudaFuncSetAttribute(k_pre_mma, cudaFuncAttributeMaxDynamicSharedMemorySize, SM_TOTAL);

    k_init<<<1, 128>>>();
    k_pre_mma<<<(NATOMS + 127) / 128, 256, SM_TOTAL>>>(atom, W, bias);
    k_rowptr<<<(NATOMS + 1 + 255) / 256, 256>>>(sidx);
    k_y_mma<<<GRID_Y, 256, SM_TOTAL>>>(nbr, sidx, nidx, W);
    k_bn1fin<<<1, DOUT>>>(g1, be1);
    k_msg<<<NATOMS / 4, 256>>>();
    k_bn2fin<<<1, ELEM>>>(g2, be2);
    k_final<<<(NATOMS * ELEM / 4 + 255) / 256, 256>>>(atom, out);
}

// round 15
// speedup vs baseline: 1.0682x; 1.0682x over previous
#include <cuda_runtime.h>
#include <cuda_bf16.h>
#include <cuda_fp16.h>
#include <math.h>
#include <stdint.h>

#define NATOMS 50000
#define NEDGES 800000
#define ELEM   64
#define DOUT   128
#define BN_EPS 1e-5f
#define NTILES (NEDGES / 128)     // 6250
#define GRID_Y 296                // persistent, 2 CTAs/SM

// ---------------- scratch (device globals; no allocation allowed) ----------------
__device__ __half g_P1h[(size_t)NATOMS * DOUT];  // atom @ W1 + b (fp16)
__device__ __half g_P2h[(size_t)NATOMS * DOUT];  // atom @ W2     (fp16)
__device__ __half g_Yh[(size_t)NEDGES * DOUT];   // pre-BN edge features, fp16
__device__ int    g_rowptr[NATOMS + 1];
__device__ float  g_colsum[DOUT];
__device__ float  g_colsq [DOUT];
__device__ float  g_a1[DOUT], g_c1[DOUT];
__device__ float  g_sumed[(size_t)NATOMS * ELEM];
__device__ float  g_s2[ELEM], g_q2[ELEM];
__device__ float  g_a2[ELEM], g_c2[ELEM];

// ---------------- helpers ----------------
__device__ __forceinline__ float softplusf(float x) {
    return log1pf(expf(-fabsf(x))) + fmaxf(x, 0.0f);
}
// round-11 gate (fast-math, short chain)
__device__ __forceinline__ float msg_gate(float yf, float yc) {
    float ef  = __expf(-yf);
    float sig = __fdividef(1.0f, 1.0f + ef);
    float ec  = __expf(-fabsf(yc));
    float sp  = __logf(1.0f + ec) + fmaxf(yc, 0.0f);
    return sig * sp;
}
__device__ __forceinline__ void mma_bf16(float4& d, uint32_t a0, uint32_t a1,
                                         uint32_t a2, uint32_t a3,
                                         uint32_t b0, uint32_t b1) {
    asm volatile(
        "mma.sync.aligned.m16n8k16.row.col.f32.bf16.bf16.f32 "
        "{%0,%1,%2,%3}, {%4,%5,%6,%7}, {%8,%9}, {%0,%1,%2,%3};"
        : "+f"(d.x), "+f"(d.y), "+f"(d.z), "+f"(d.w)
        : "r"(a0), "r"(a1), "r"(a2), "r"(a3), "r"(b0), "r"(b1));
}
__device__ __forceinline__ uint32_t bf2_bits(__nv_bfloat162 h) {
    return *reinterpret_cast<uint32_t*>(&h);
}
__device__ __forceinline__ uint32_t h2_bits(__half2 h) {
    return *reinterpret_cast<uint32_t*>(&h);
}

// ---------------- SMEM layout (bytes), shared by k_y_mma and k_pre_mma ----------------
#define LDAB 72           // bf16 A leading dim (144B rows -> conflict-free lds.32)
#define NPAD 20           // B packed: uint4 slots per n (320B stride)
#define SM_SIDX 0         // 128 ints
#define SM_NIDX 512
#define SM_AH   1024      // 128 x LDAB bf16 = 18432
#define SM_AL   19456     // 128 x LDAB bf16 = 18432
#define SM_BP   37888     // packed B: 128 x NPAD x 16B = 40960
#define SM_TOTAL 78848    // 77 KB -> 2 CTAs/SM

// ---------------- kernels ----------------
__global__ void k_init() {
    int t = threadIdx.x;
    if (t < DOUT) { g_colsum[t] = 0.f; g_colsq[t] = 0.f; }
    if (t < ELEM) { g_s2[t] = 0.f; g_q2[t] = 0.f; }
}

__global__ void k_rowptr(const int* __restrict__ sidx) {
    int a = blockIdx.x * blockDim.x + threadIdx.x;
    if (a > NATOMS) return;
    int lo = 0, hi = NEDGES;
    while (lo < hi) {
        int mid = (lo + hi) >> 1;
        if (sidx[mid] < a) lo = mid + 1; else hi = mid;
    }
    g_rowptr[a] = lo;
}

// Precompute via HMMA: P1 = atom @ W[0:64] + b (phase 0), P2 = atom @ W[64:128].
__global__ void __launch_bounds__(256, 2) k_pre_mma(const float* __restrict__ atom,
                                                    const float* __restrict__ W,
                                                    const float* __restrict__ bias) {
    extern __shared__ char sm[];
    __nv_bfloat16* sAh = (__nv_bfloat16*)(sm + SM_AH);
    __nv_bfloat16* sAl = (__nv_bfloat16*)(sm + SM_AL);
    uint4* sBp = (uint4*)(sm + SM_BP);

    const int tid  = threadIdx.x;
    const int wid  = tid >> 5;
    const int lane = tid & 31;
    const int wm   = wid >> 1;
    const int wn   = wid & 1;
    const int g    = lane >> 2;
    const int tg   = lane & 3;
    const int colbase = wn * 64 + tg * 16;

    const int ab = blockIdx.x * 128;
    const int nvalid = min(128, NATOMS - ab);

    #pragma unroll
    for (int p = 0; p < 8; p++) {
        int i4 = tid + p * 256;
        int row = i4 >> 4, kv = i4 & 15;
        float4 v = make_float4(0.f, 0.f, 0.f, 0.f);
        if (row < nvalid)
            v = __ldg((const float4*)(atom + (size_t)(ab + row) * ELEM + kv * 4));
        __nv_bfloat162 h0 = __float22bfloat162_rn(make_float2(v.x, v.y));
        __nv_bfloat162 h1 = __float22bfloat162_rn(make_float2(v.z, v.w));
        __nv_bfloat162 l0 = __float22bfloat162_rn(make_float2(
            v.x - __bfloat162float(__low2bfloat16(h0)),
            v.y - __bfloat162float(__high2bfloat16(h0))));
        __nv_bfloat162 l1 = __float22bfloat162_rn(make_float2(
            v.z - __bfloat162float(__low2bfloat16(h1)),
            v.w - __bfloat162float(__high2bfloat16(h1))));
        int o = row * LDAB + kv * 4;
        uint2 oh; oh.x = bf2_bits(h0); oh.y = bf2_bits(h1);
        uint2 ol; ol.x = bf2_bits(l0); ol.y = bf2_bits(l1);
        *(uint2*)(sAh + o) = oh;
        *(uint2*)(sAl + o) = ol;
    }

    float4 bj[4];
    #pragma unroll
    for (int q = 0; q < 4; q++)
        bj[q] = __ldg((const float4*)(bias + colbase + q * 4));

    for (int phase = 0; phase < 2; phase++) {
        #pragma unroll
        for (int it = 0; it < 8; it++) {
            int idx = it * 256 + tid;
            int n   = idx >> 4;
            int ks  = (idx >> 2) & 3;
            int tgq = idx & 3;
            int h = n >> 6, pp = n & 63;
            int l = ((pp >> 1) & 3) * 16 + (pp >> 3) * 2 + (pp & 1);
            int col = h * 64 + l;
            int k0 = ks * 16 + tgq * 2;
            float v0 = W[(size_t)(phase * 64 + k0)     * DOUT + col];
            float v1 = W[(size_t)(phase * 64 + k0 + 1) * DOUT + col];
            float v2 = W[(size_t)(phase * 64 + k0 + 8) * DOUT + col];
            float v3 = W[(size_t)(phase * 64 + k0 + 9) * DOUT + col];
            __nv_bfloat162 h01 = __float22bfloat162_rn(make_float2(v0, v1));
            __nv_bfloat162 h23 = __float22bfloat162_rn(make_float2(v2, v3));
            __nv_bfloat162 l01 = __float22bfloat162_rn(make_float2(
                v0 - __bfloat162float(__low2bfloat16(h01)), v1 - __bfloat162float(__high2bfloat16(h01))));
            __nv_bfloat162 l23 = __float22bfloat162_rn(make_float2(
                v2 - __bfloat162float(__low2bfloat16(h23)), v3 - __bfloat162float(__high2bfloat16(h23))));
            uint4 o;
            o.x = bf2_bits(h01); o.y = bf2_bits(h23);
            o.z = bf2_bits(l01); o.w = bf2_bits(l23);
            sBp[(size_t)n * NPAD + ks * 4 + tgq] = o;
        }
        __syncthreads();

        float4 acc[2][8];
        #pragma unroll
        for (int i = 0; i < 2; i++)
            #pragma unroll
            for (int j = 0; j < 8; j++)
                acc[i][j] = make_float4(0.f, 0.f, 0.f, 0.f);

        #pragma unroll
        for (int ks = 0; ks < 4; ks++) {
            const int c0 = ks * 16 + tg * 2;
            uint32_t ah[2][4], al[2][4];
            #pragma unroll
            for (int i = 0; i < 2; i++) {
                const __nv_bfloat16* rh = sAh + (wm * 32 + i * 16 + g) * LDAB;
                const __nv_bfloat16* rl = sAl + (wm * 32 + i * 16 + g) * LDAB;
                ah[i][0] = *(const uint32_t*)(rh + c0);
                ah[i][1] = *(const uint32_t*)(rh + 8 * LDAB + c0);
                ah[i][2] = *(const uint32_t*)(rh + c0 + 8);
                ah[i][3] = *(const uint32_t*)(rh + 8 * LDAB + c0 + 8);
                al[i][0] = *(const uint32_t*)(rl + c0);
                al[i][1] = *(const uint32_t*)(rl + 8 * LDAB + c0);
                al[i][2] = *(const uint32_t*)(rl + c0 + 8);
                al[i][3] = *(const uint32_t*)(rl + 8 * LDAB + c0 + 8);
            }
            #pragma unroll
            for (int j = 0; j < 8; j++) {
                const int n = wn * 64 + j * 8 + g;
                uint4 bb = sBp[(size_t)n * NPAD + ks * 4 + tg];
                #pragma unroll
                for (int i = 0; i < 2; i++) {
                    mma_bf16(acc[i][j], ah[i][0], ah[i][1], ah[i][2], ah[i][3], bb.x, bb.y);
                    mma_bf16(acc[i][j], ah[i][0], ah[i][1], ah[i][2], ah[i][3], bb.z, bb.w);
                    mma_bf16(acc[i][j], al[i][0], al[i][1], al[i][2], al[i][3], bb.x, bb.y);
                }
            }
        }

        __half* Pdst = (phase == 0) ? g_P1h : g_P2h;
        #pragma unroll
        for (int i = 0; i < 2; i++) {
            #pragma unroll
            for (int rr = 0; rr < 2; rr++) {
                const int row = wm * 32 + i * 16 + rr * 8 + g;
                if (row < nvalid) {
                    uint32_t hb[8];
                    #pragma unroll
                    for (int j = 0; j < 8; j++) {
                        float y0 = (rr ? acc[i][j].z : acc[i][j].x);
                        float y1 = (rr ? acc[i][j].w : acc[i][j].y);
                        if (phase == 0) {
                            float bx = (j & 1) ? bj[j >> 1].z : bj[j >> 1].x;
                            float by = (j & 1) ? bj[j >> 1].w : bj[j >> 1].y;
                            y0 += bx; y1 += by;
                        }
                        hb[j] = h2_bits(__floats2half2_rn(y0, y1));
                    }
                    uint4 o0 = make_uint4(hb[0], hb[1], hb[2], hb[3]);
                    uint4 o1 = make_uint4(hb[4], hb[5], hb[6], hb[7]);
                    __half* dst = Pdst + (size_t)(ab + row) * DOUT + colbase;
                    *(uint4*)dst       = o0;
                    *(uint4*)(dst + 8) = o1;
                }
            }
        }
        __syncthreads();
    }
}

// Pass 1 (raw HMMA): unchanged from round 13.
__global__ void __launch_bounds__(256, 2) k_y_mma(const float* __restrict__ nbr,
                                                  const int* __restrict__ sidx,
                                                  const int* __restrict__ nidx,
                                                  const float* __restrict__ W) {
    extern __shared__ char sm[];
    int*   s_sidx = (int*)(sm + SM_SIDX);
    int*   s_nidx = (int*)(sm + SM_NIDX);
    __nv_bfloat16* sAh = (__nv_bfloat16*)(sm + SM_AH);
    __nv_bfloat16* sAl = (__nv_bfloat16*)(sm + SM_AL);
    uint4* sBp = (uint4*)(sm + SM_BP);

    const int tid  = threadIdx.x;
    const int wid  = tid >> 5;
    const int lane = tid & 31;
    const int wm   = wid >> 1;
    const int wn   = wid & 1;
    const int g    = lane >> 2;
    const int tg   = lane & 3;

    #pragma unroll
    for (int it = 0; it < 8; it++) {
        int idx = it * 256 + tid;
        int n   = idx >> 4;
        int ks  = (idx >> 2) & 3;
        int tgq = idx & 3;
        int h = n >> 6, pp = n & 63;
        int l = ((pp >> 1) & 3) * 16 + (pp >> 3) * 2 + (pp & 1);
        int col = h * 64 + l;
        int k0 = ks * 16 + tgq * 2;
        float v0 = W[(size_t)(128 + k0)     * DOUT + col];
        float v1 = W[(size_t)(128 + k0 + 1) * DOUT + col];
        float v2 = W[(size_t)(128 + k0 + 8) * DOUT + col];
        float v3 = W[(size_t)(128 + k0 + 9) * DOUT + col];
        __nv_bfloat162 h01 = __float22bfloat162_rn(make_float2(v0, v1));
        __nv_bfloat162 h23 = __float22bfloat162_rn(make_float2(v2, v3));
        __nv_bfloat162 l01 = __float22bfloat162_rn(make_float2(
            v0 - __bfloat162float(__low2bfloat16(h01)), v1 - __bfloat162float(__high2bfloat16(h01))));
        __nv_bfloat162 l23 = __float22bfloat162_rn(make_float2(
            v2 - __bfloat162float(__low2bfloat16(h23)), v3 - __bfloat162float(__high2bfloat16(h23))));
        uint4 o;
        o.x = bf2_bits(h01); o.y = bf2_bits(h23);
        o.z = bf2_bits(l01); o.w = bf2_bits(l23);
        sBp[(size_t)n * NPAD + ks * 4 + tgq] = o;
    }
    __syncthreads();

    float cs[16], cq[16];
    #pragma unroll
    for (int q = 0; q < 16; q++) { cs[q] = 0.f; cq[q] = 0.f; }
    const int colbase = wn * 64 + tg * 16;

    for (int t = blockIdx.x; t < NTILES; t += GRID_Y) {
        const int eb = t * 128;

        float4 v[8];
        #pragma unroll
        for (int p = 0; p < 8; p++)
            v[p] = __ldcs((const float4*)(nbr + (size_t)eb * ELEM) + tid + p * 256);
        if (tid < 128) {
            s_sidx[tid] = __ldg(sidx + eb + tid);
            s_nidx[tid] = __ldg(nidx + eb + tid);
        }
        #pragma unroll
        for (int p = 0; p < 8; p++) {
            int i4 = tid + p * 256;
            int row = i4 >> 4, kv = i4 & 15;
            __nv_bfloat162 h0 = __float22bfloat162_rn(make_float2(v[p].x, v[p].y));
            __nv_bfloat162 h1 = __float22bfloat162_rn(make_float2(v[p].z, v[p].w));
            __nv_bfloat162 l0 = __float22bfloat162_rn(make_float2(
                v[p].x - __bfloat162float(__low2bfloat16(h0)),
                v[p].y - __bfloat162float(__high2bfloat16(h0))));
            __nv_bfloat162 l1 = __float22bfloat162_rn(make_float2(
                v[p].z - __bfloat162float(__low2bfloat16(h1)),
                v[p].w - __bfloat162float(__high2bfloat16(h1))));
            int o = row * LDAB + kv * 4;
            uint2 oh; oh.x = bf2_bits(h0); oh.y = bf2_bits(h1);
            uint2 ol; ol.x = bf2_bits(l0); ol.y = bf2_bits(l1);
            *(uint2*)(sAh + o) = oh;
            *(uint2*)(sAl + o) = ol;
        }
        __syncthreads();

        float4 acc[2][8];
        #pragma unroll
        for (int i = 0; i < 2; i++)
            #pragma unroll
            for (int j = 0; j < 8; j++)
                acc[i][j] = make_float4(0.f, 0.f, 0.f, 0.f);

        #pragma unroll
        for (int ks = 0; ks < 4; ks++) {
            const int c0 = ks * 16 + tg * 2;
            uint32_t ah[2][4], al[2][4];
            #pragma unroll
            for (int i = 0; i < 2; i++) {
                const __nv_bfloat16* rh = sAh + (wm * 32 + i * 16 + g) * LDAB;
                const __nv_bfloat16* rl = sAl + (wm * 32 + i * 16 + g) * LDAB;
                ah[i][0] = *(const uint32_t*)(rh + c0);
                ah[i][1] = *(const uint32_t*)(rh + 8 * LDAB + c0);
                ah[i][2] = *(const uint32_t*)(rh + c0 + 8);
                ah[i][3] = *(const uint32_t*)(rh + 8 * LDAB + c0 + 8);
                al[i][0] = *(const uint32_t*)(rl + c0);
                al[i][1] = *(const uint32_t*)(rl + 8 * LDAB + c0);
                al[i][2] = *(const uint32_t*)(rl + c0 + 8);
                al[i][3] = *(const uint32_t*)(rl + 8 * LDAB + c0 + 8);
            }
            #pragma unroll
            for (int j = 0; j < 8; j++) {
                const int n = wn * 64 + j * 8 + g;
                uint4 bb = sBp[(size_t)n * NPAD + ks * 4 + tg];
                #pragma unroll
                for (int i = 0; i < 2; i++) {
                    mma_bf16(acc[i][j], ah[i][0], ah[i][1], ah[i][2], ah[i][3], bb.x, bb.y);
                    mma_bf16(acc[i][j], ah[i][0], ah[i][1], ah[i][2], ah[i][3], bb.z, bb.w);
                    mma_bf16(acc[i][j], al[i][0], al[i][1], al[i][2], al[i][3], bb.x, bb.y);
                }
            }
        }

        #pragma unroll
        for (int i = 0; i < 2; i++) {
            #pragma unroll
            for (int rr = 0; rr < 2; rr++) {
                const int row = wm * 32 + i * 16 + rr * 8 + g;
                const int s = s_sidx[row], n = s_nidx[row];
                uint4 p1u[2], p2u[2];
                p1u[0] = __ldg((const uint4*)(g_P1h + (size_t)s * DOUT + colbase));
                p1u[1] = __ldg((const uint4*)(g_P1h + (size_t)s * DOUT + colbase + 8));
                p2u[0] = __ldg((const uint4*)(g_P2h + (size_t)n * DOUT + colbase));
                p2u[1] = __ldg((const uint4*)(g_P2h + (size_t)n * DOUT + colbase + 8));
                const __half2* ph1 = (const __half2*)p1u;
                const __half2* ph2 = (const __half2*)p2u;
                uint32_t hb[8];
                #pragma unroll
                for (int j = 0; j < 8; j++) {
                    float2 p1 = __half22float2(ph1[j]);
                    float2 p2 = __half22float2(ph2[j]);
                    float y0 = (rr ? acc[i][j].z : acc[i][j].x) + p1.x + p2.x;
                    float y1 = (rr ? acc[i][j].w : acc[i][j].y) + p1.y + p2.y;
                    cs[2 * j]     += y0; cq[2 * j]     += y0 * y0;
                    cs[2 * j + 1] += y1; cq[2 * j + 1] += y1 * y1;
                    hb[j] = h2_bits(__floats2half2_rn(y0, y1));
                }
                float4 o0 = make_float4(__uint_as_float(hb[0]), __uint_as_float(hb[1]),
                                        __uint_as_float(hb[2]), __uint_as_float(hb[3]));
                float4 o1 = make_float4(__uint_as_float(hb[4]), __uint_as_float(hb[5]),
                                        __uint_as_float(hb[6]), __uint_as_float(hb[7]));
                __half* yr = g_Yh + (size_t)(eb + row) * DOUT + colbase;
                __stcs((float4*)yr, o0);
                __stcs((float4*)(yr + 8), o1);
            }
        }
        __syncthreads();
    }

    #pragma unroll
    for (int q = 0; q < 16; q++) {
        cs[q] += __shfl_xor_sync(0xffffffff, cs[q], 4);
        cs[q] += __shfl_xor_sync(0xffffffff, cs[q], 8);
        cs[q] += __shfl_xor_sync(0xffffffff, cs[q], 16);
        cq[q] += __shfl_xor_sync(0xffffffff, cq[q], 4);
        cq[q] += __shfl_xor_sync(0xffffffff, cq[q], 8);
        cq[q] += __shfl_xor_sync(0xffffffff, cq[q], 16);
    }
    if (g == 0) {
        #pragma unroll
        for (int q = 0; q < 16; q++) {
            atomicAdd(&g_colsum[colbase + q], cs[q]);
            atomicAdd(&g_colsq[colbase + q],  cq[q]);
        }
    }
}

__global__ void k_bn1fin(const float* __restrict__ gamma, const float* __restrict__ beta) {
    int j = threadIdx.x;
    float mean = g_colsum[j] * (1.0f / NEDGES);
    float var  = g_colsq[j] * (1.0f / NEDGES) - mean * mean;
    float aa = gamma[j] * rsqrtf(var + BN_EPS);
    g_a1[j] = aa;
    g_c1[j] = beta[j] - mean * aa;
}

// Pass 2 (round-13 structure, 2x edge unroll for MLP): warp per atom,
// lane = (quarter, 8 cols); per iteration process edges e, e+4 while
// prefetching e+8, e+12.
__global__ void __launch_bounds__(256) k_msg() {
    __shared__ float sS[ELEM], sQ[ELEM];
    const int lane = threadIdx.x;
    const int tid  = threadIdx.y * 32 + lane;
    const int a = blockIdx.x * 8 + threadIdx.y;   // grid*8 == NATOMS
    if (tid < ELEM) { sS[tid] = 0.f; sQ[tid] = 0.f; }
    __syncthreads();

    const int quarter = lane >> 3;
    const int j8 = lane & 7;

    float a1f[8], c1f[8], a1c[8], c1c[8];
    #pragma unroll
    for (int q = 0; q < 8; q++) {
        int j = 8 * j8 + q;
        a1f[q] = g_a1[j];      c1f[q] = g_c1[j];
        a1c[q] = g_a1[64 + j]; c1c[q] = g_c1[64 + j];
    }

    const int e0 = g_rowptr[a], e1 = g_rowptr[a + 1];
    float s[8];
    #pragma unroll
    for (int q = 0; q < 8; q++) s[q] = 0.f;
    const char* Yb = (const char*)g_Yh;

    int e = e0 + quarter;
    float4 fa, ca, fb, cb;
    if (e < e1) {
        fa = __ldcs((const float4*)(Yb + (size_t)e * 256 + j8 * 16));
        ca = __ldcs((const float4*)(Yb + (size_t)e * 256 + 128 + j8 * 16));
    }
    if (e + 4 < e1) {
        fb = __ldcs((const float4*)(Yb + (size_t)(e + 4) * 256 + j8 * 16));
        cb = __ldcs((const float4*)(Yb + (size_t)(e + 4) * 256 + 128 + j8 * 16));
    }
    while (e < e1) {
        float4 fc, cc, fd, cd;
        if (e + 8 < e1) {
            fc = __ldcs((const float4*)(Yb + (size_t)(e + 8) * 256 + j8 * 16));
            cc = __ldcs((const float4*)(Yb + (size_t)(e + 8) * 256 + 128 + j8 * 16));
        }
        if (e + 12 < e1) {
            fd = __ldcs((const float4*)(Yb + (size_t)(e + 12) * 256 + j8 * 16));
            cd = __ldcs((const float4*)(Yb + (size_t)(e + 12) * 256 + 128 + j8 * 16));
        }
        {
            const __half2* f2 = (const __half2*)&fa;
            const __half2* c2 = (const __half2*)&ca;
            #pragma unroll
            for (int p = 0; p < 4; p++) {
                float yf0 = __low2float(f2[p])  * a1f[2*p]   + c1f[2*p];
                float yc0 = __low2float(c2[p])  * a1c[2*p]   + c1c[2*p];
                s[2*p]   += msg_gate(yf0, yc0);
                float yf1 = __high2float(f2[p]) * a1f[2*p+1] + c1f[2*p+1];
                float yc1 = __high2float(c2[p]) * a1c[2*p+1] + c1c[2*p+1];
                s[2*p+1] += msg_gate(yf1, yc1);
            }
        }
        if (e + 4 < e1) {
            const __half2* f2 = (const __half2*)&fb;
            const __half2* c2 = (const __half2*)&cb;
            #pragma unroll
            for (int p = 0; p < 4; p++) {
                float yf0 = __low2float(f2[p])  * a1f[2*p]   + c1f[2*p];
                float yc0 = __low2float(c2[p])  * a1c[2*p]   + c1c[2*p];
                s[2*p]   += msg_gate(yf0, yc0);
                float yf1 = __high2float(f2[p]) * a1f[2*p+1] + c1f[2*p+1];
                float yc1 = __high2float(c2[p]) * a1c[2*p+1] + c1c[2*p+1];
                s[2*p+1] += msg_gate(yf1, yc1);
            }
        }
        fa = fc; ca = cc; fb = fd; cb = cd;
        e += 8;
    }
    #pragma unroll
    for (int q = 0; q < 8; q++) {
        s[q] += __shfl_xor_sync(0xffffffff, s[q], 8);
        s[q] += __shfl_xor_sync(0xffffffff, s[q], 16);
    }
    if (quarter == 0) {
        float4 st0 = make_float4(s[0], s[1], s[2], s[3]);
        float4 st1 = make_float4(s[4], s[5], s[6], s[7]);
        *(float4*)&g_sumed[(size_t)a * ELEM + j8 * 8]     = st0;
        *(float4*)&g_sumed[(size_t)a * ELEM + j8 * 8 + 4] = st1;
        #pragma unroll
        for (int q = 0; q < 8; q++) {
            atomicAdd(&sS[8 * j8 + q], s[q]);
            atomicAdd(&sQ[8 * j8 + q], s[q] * s[q]);
        }
    }
    __syncthreads();
    if (tid < ELEM) {
        atomicAdd(&g_s2[tid], sS[tid]);
        atomicAdd(&g_q2[tid], sQ[tid]);
    }
}

__global__ void k_bn2fin(const float* __restrict__ gamma, const float* __restrict__ beta) {
    int j = threadIdx.x;
    float mean = g_s2[j] * (1.0f / NATOMS);
    float var  = g_q2[j] * (1.0f / NATOMS) - mean * mean;
    float aa = gamma[j] * rsqrtf(var + BN_EPS);
    g_a2[j] = aa;
    g_c2[j] = beta[j] - mean * aa;
}

__global__ void k_final(const float* __restrict__ atom, float* __restrict__ out) {
    int i4 = blockIdx.x * blockDim.x + threadIdx.x;
    if (i4 >= NATOMS * ELEM / 4) return;
    int base = i4 * 4;
    int j = base & 63;
    float4 av = *(const float4*)(atom + base);
    float4 sv = *(const float4*)(g_sumed + base);
    float4 o;
    o.x = softplusf(av.x + sv.x * g_a2[j]     + g_c2[j]);
    o.y = softplusf(av.y + sv.y * g_a2[j + 1] + g_c2[j + 1]);
    o.z = softplusf(av.z + sv.z * g_a2[j + 2] + g_c2[j + 2]);
    o.w = softplusf(av.w + sv.w * g_a2[j + 3] + g_c2[j + 3]);
    *(float4*)(out + base) = o;
}

// ---------------- launch ----------------
extern "C" void kernel_launch(void* const* d_in, const int* in_sizes, int n_in,
                              void* d_out, int out_size) {
    const float* atom = (const float*)d_in[0];
    const float* nbr  = (const float*)d_in[1];
    const int*   sidx = (const int*)d_in[2];
    const int*   nidx = (const int*)d_in[3];
    const float* W    = (const float*)d_in[4];
    const float* bias = (const float*)d_in[5];
    const float* g1   = (const float*)d_in[6];
    const float* be1  = (const float*)d_in[7];
    const float* g2   = (const float*)d_in[8];
    const float* be2  = (const float*)d_in[9];
    float* out = (float*)d_out;

    cudaFuncSetAttribute(k_y_mma, cudaFuncAttributeMaxDynamicSharedMemorySize, SM_TOTAL);
    cudaFuncSetAttribute(k_pre_mma, cudaFuncAttributeMaxDynamicSharedMemorySize, SM_TOTAL);

    k_init<<<1, 128>>>();
    k_pre_mma<<<(NATOMS + 127) / 128, 256, SM_TOTAL>>>(atom, W, bias);
    k_rowptr<<<(NATOMS + 1 + 255) / 256, 256>>>(sidx);
    k_y_mma<<<GRID_Y, 256, SM_TOTAL>>>(nbr, sidx, nidx, W);
    k_bn1fin<<<1, DOUT>>>(g1, be1);
    dim3 mblk(32, 8);
    k_msg<<<NATOMS / 8, mblk>>>();
    k_bn2fin<<<1, ELEM>>>(g2, be2);
    k_final<<<(NATOMS * ELEM / 4 + 255) / 256, 256>>>(atom, out);
}